// round 8
// baseline (speedup 1.0000x reference)
#include <cuda_runtime.h>
#include <cstdint>

// Problem constants
#define BB 8            // clouds
#define NN 4096         // points per cloud
#define M1 1024         // ceil(0.25*4096) base fps picks per cloud
#define M2 820          // ceil(0.20*4096) extra fps picks per cloud
#define OVSZ 1638       // int(8*1024*0.2) : extra picks kept
#define MTOT 9830       // BB*M1 + OVSZ
#define KNN 16

#define CPC 4           // CTAs per cloud (cluster size)
#define FT 256          // threads per fps CTA
#define LPT 4           // points per thread (1024 / 256)
#define NSLOT 32        // CPC * 8 warps
#define SLOTB 32        // bytes per slot (key u64, xy u64, z u64, pad)
#define TXB (NSLOT * 24)  // expected tx bytes per step per CTA

typedef unsigned long long u64;

// Internal int-valued combined indices (kNN consumes these; d_out is float32).
__device__ int g_cidx[MTOT];

// Packed f32x2 helpers (two rn.f32 ops in one instruction, bit-identical)
#define ADD2(out, a, b) asm("add.rn.f32x2 %0, %1, %2;" : "=l"(out) : "l"(a), "l"(b))
#define MUL2(out, a, b) asm("mul.rn.f32x2 %0, %1, %2;" : "=l"(out) : "l"(a), "l"(b))
#define PACK2(out, lo, hi) asm("mov.b64 %0, {%1, %2};" : "=l"(out) : "r"(lo), "r"(hi))
#define UNPK2(lo, hi, in)  asm("mov.b64 {%0, %1}, %2;" : "=r"(lo), "=r"(hi) : "l"(in))

__device__ __forceinline__ uint32_t smem_u32(const void* p) {
    uint32_t a;
    asm("{ .reg .u64 t; cvta.to.shared.u64 t, %1; cvt.u32.u64 %0, t; }"
        : "=r"(a) : "l"(p));
    return a;
}

__device__ __forceinline__ uint32_t ctarank() {
    uint32_t r;
    asm("mov.u32 %0, %%cluster_ctarank;" : "=r"(r));
    return r;
}

__device__ __forceinline__ uint32_t mapa_u32(uint32_t addr, uint32_t rank) {
    uint32_t r;
    asm("mapa.shared::cluster.u32 %0, %1, %2;" : "=r"(r) : "r"(addr), "r"(rank));
    return r;
}

__device__ __forceinline__ void st_async_b64(uint32_t raddr, u64 v, uint32_t rbar) {
    asm volatile(
        "st.async.shared::cluster.mbarrier::complete_tx::bytes.b64 [%0], %1, [%2];"
        :: "r"(raddr), "l"(v), "r"(rbar) : "memory");
}

__device__ __forceinline__ void mbar_init(uint32_t bar, uint32_t cnt) {
    asm volatile("mbarrier.init.shared.b64 [%0], %1;" :: "r"(bar), "r"(cnt) : "memory");
}

__device__ __forceinline__ void mbar_expect_tx(uint32_t bar, uint32_t bytes) {
    asm volatile("mbarrier.arrive.expect_tx.shared.b64 _, [%0], %1;"
                 :: "r"(bar), "r"(bytes) : "memory");
}

__device__ __forceinline__ void mbar_wait(uint32_t bar, uint32_t parity) {
    uint32_t done;
    asm volatile(
        "{\n\t.reg .pred p;\n\t"
        "mbarrier.try_wait.parity.acquire.cta.shared::cta.b64 p, [%1], %2;\n\t"
        "selp.b32 %0, 1, 0, p;\n\t}"
        : "=r"(done) : "r"(bar), "r"(parity) : "memory");
    if (!done) {
        asm volatile(
            "{\n\t.reg .pred P1;\n\t"
            "WL_%=:\n\t"
            "mbarrier.try_wait.parity.acquire.cta.shared::cta.b64 P1, [%0], %1, 0x989680;\n\t"
            "@P1 bra.uni WD_%=;\n\t"
            "bra.uni WL_%=;\n\t"
            "WD_%=:\n\t}"
            :: "r"(bar), "r"(parity) : "memory");
    }
}

// -------------------------------------------------------------------------
// FPS: 4-CTA cluster per cloud (32 CTAs). CTA r owns points
// [1024r, 1024r+1024), thread t owns 4 contiguous points (registers).
// Per step:
//   - packed f32x2 distance + running min (exact), per-thread argmax
//     (ascending, strict > -> smallest-idx ties)
//   - warp REDUX max + first-tied-lane leader; leader posts
//     {key=(dist<<32)|(NN-1-idx), coords} (24B) via st.async to the slot
//     buffer of ALL 4 CTAs (cluster DSMEM), completing each CTA's mbarrier
//   - each CTA waits its local mbarrier (expect 32*24B), then every warp
//     scans the 32 slot keys (lane=slot) with 2 REDUX passes; winner
//     coords come from the winning slot (no gmem dependency).
// Parity double-buffered slots+barriers (peer at most 1 step ahead).
// m2 extra-fps picks are a prefix of the m1 sequence -> one pass emits all.
// -------------------------------------------------------------------------
__global__ void __launch_bounds__(FT, 1) __cluster_dims__(CPC, 1, 1)
fps_kernel(const float* __restrict__ pos, float* __restrict__ outf)
{
    __shared__ __align__(16) unsigned char slots[2][NSLOT * SLOTB];
    __shared__ __align__(8)  u64 bars[2];

    const int t    = threadIdx.x;
    const int warp = t >> 5, lane = t & 31;
    const unsigned full = 0xffffffffu;
    const uint32_t rank  = ctarank();
    const int      cloud = blockIdx.x / CPC;

    const uint32_t sl0 = smem_u32(&slots[0][0]);
    const uint32_t sl1 = smem_u32(&slots[1][0]);
    const uint32_t bar0 = smem_u32(&bars[0]);
    const uint32_t bar1 = smem_u32(&bars[1]);

    if (t == 0) {
        mbar_init(bar0, 1);
        mbar_init(bar1, 1);
        mbar_expect_tx(bar1, TXB);   // step 1 (idx = 1)
        mbar_expect_tx(bar0, TXB);   // step 2 (idx = 0)
    }
    __syncthreads();
    asm volatile("barrier.cluster.arrive.aligned;" ::: "memory");
    asm volatile("barrier.cluster.wait.aligned;"   ::: "memory");

    // Remote addresses for my warp's slot (index = rank*8 + warp), all 4 CTAs.
    const int myslot = (int)rank * 8 + warp;
    uint32_t rs0[CPC], rs1[CPC], rb0[CPC], rb1[CPC];
#pragma unroll
    for (int r = 0; r < CPC; ++r) {
        rs0[r] = mapa_u32(sl0 + myslot * SLOTB, r);
        rs1[r] = mapa_u32(sl1 + myslot * SLOTB, r);
        rb0[r] = mapa_u32(bar0, r);
        rb1[r] = mapa_u32(bar1, r);
    }

    const float* __restrict__ p = pos + (size_t)cloud * NN * 3;
    const int base = (int)rank * 1024 + t * LPT;   // cloud-local, contiguous

    u64 rx2[2], ry2[2], rz2[2];
    float mind[LPT];
#pragma unroll
    for (int m = 0; m < 2; ++m) {
        int i0 = base + 2 * m;
        float x0 = p[3 * i0 + 0], y0 = p[3 * i0 + 1], z0 = p[3 * i0 + 2];
        float x1 = p[3 * i0 + 3], y1 = p[3 * i0 + 4], z1 = p[3 * i0 + 5];
        PACK2(rx2[m], __float_as_uint(x0), __float_as_uint(x1));
        PACK2(ry2[m], __float_as_uint(y0), __float_as_uint(y1));
        PACK2(rz2[m], __float_as_uint(z0), __float_as_uint(z1));
        mind[2 * m]     = __int_as_float(0x7f800000);
        mind[2 * m + 1] = __int_as_float(0x7f800000);
    }

    if (rank == 0 && t == 0) {
        int g0 = cloud * NN;
        g_cidx[cloud * M1] = g0;  outf[cloud * M1] = (float)g0;
        if (cloud == 0) { g_cidx[BB * M1]      = 0;  outf[BB * M1]      = 0.0f; }
        if (cloud == 1) { g_cidx[BB * M1 + M2] = NN; outf[BB * M1 + M2] = (float)NN; }
    }

    // Pick 0 coords
    float lx = __ldg(&p[0]);
    float ly = __ldg(&p[1]);
    float lz = __ldg(&p[2]);

    int ph0 = 0, ph1 = 0;

    for (int s = 1; s < M1; ++s) {
        u64 nlx2, nly2, nlz2;
        {
            unsigned nx = __float_as_uint(-lx);
            unsigned ny = __float_as_uint(-ly);
            unsigned nz = __float_as_uint(-lz);
            PACK2(nlx2, nx, nx);
            PACK2(nly2, ny, ny);
            PACK2(nlz2, nz, nz);
        }

        float bestv = -1.0f;
        int   bestk = 0;
#pragma unroll
        for (int m = 0; m < 2; ++m) {
            u64 dx2, dy2, dz2, xx2, yy2, zz2, t2, s2;
            ADD2(dx2, rx2[m], nlx2);
            ADD2(dy2, ry2[m], nly2);
            ADD2(dz2, rz2[m], nlz2);
            MUL2(xx2, dx2, dx2);
            MUL2(yy2, dy2, dy2);
            MUL2(zz2, dz2, dz2);
            ADD2(t2, xx2, yy2);
            ADD2(s2, t2, zz2);
            unsigned b0, b1;
            UNPK2(b0, b1, s2);
            float m0 = fminf(mind[2 * m],     __uint_as_float(b0));
            float m1 = fminf(mind[2 * m + 1], __uint_as_float(b1));
            mind[2 * m]     = m0;
            mind[2 * m + 1] = m1;
            if (m0 > bestv) { bestv = m0; bestk = 2 * m;     }
            if (m1 > bestv) { bestv = m1; bestk = 2 * m + 1; }
        }

        // Warp argmax; first tied lane (lowest lane = lowest idx) is leader.
        unsigned bv   = __float_as_uint(bestv);
        unsigned wmax = __reduce_max_sync(full, bv);
        unsigned tied = __ballot_sync(full, bv == wmax);
        if ((bv == wmax) && ((tied & ((1u << lane) - 1u)) == 0u)) {
            // Extract candidate coords from registers
            unsigned x0, x1, y0, y1, z0, z1;
            UNPK2(x0, x1, rx2[bestk >> 1]);
            UNPK2(y0, y1, ry2[bestk >> 1]);
            UNPK2(z0, z1, rz2[bestk >> 1]);
            unsigned cx = (bestk & 1) ? x1 : x0;
            unsigned cy = (bestk & 1) ? y1 : y0;
            unsigned cz = (bestk & 1) ? z1 : z0;
            u64 key = ((u64)wmax << 32) | (unsigned)(NN - 1 - (base + bestk));
            u64 xy, zz;
            PACK2(xy, cx, cy);
            PACK2(zz, cz, 0u);
            const int par = s & 1;
#pragma unroll
            for (int r = 0; r < CPC; ++r) {
                uint32_t ra = par ? rs1[r] : rs0[r];
                uint32_t rb = par ? rb1[r] : rb0[r];
                st_async_b64(ra,      key, rb);
                st_async_b64(ra + 8,  xy,  rb);
                st_async_b64(ra + 16, zz,  rb);
            }
        }

        // Wait for all 32 partials of this step
        const int par = s & 1;
        const uint32_t mybar = par ? bar1 : bar0;
        mbar_wait(mybar, par ? ph1 : ph0);
        if (t == 0) mbar_expect_tx(mybar, TXB);   // re-arm for step s+2
        if (par) ph1 ^= 1; else ph0 ^= 1;

        // Scan: lane l holds slot l's key; 2-stage REDUX picks winner.
        const uint32_t slb = par ? sl1 : sl0;
        u64 k;
        asm volatile("ld.shared.b64 %0, [%1];" : "=l"(k) : "r"(slb + lane * SLOTB));
        unsigned hi = (unsigned)(k >> 32);
        unsigned lo = (unsigned)k;
        unsigned m  = __reduce_max_sync(full, hi);
        unsigned cl = (hi == m) ? lo : 0u;
        unsigned wlo = __reduce_max_sync(full, cl);   // max(NN-1-idx) == min idx
        int win = NN - 1 - (int)wlo;

        // Winning slot -> coords (broadcast LDS)
        unsigned wsb = __ballot_sync(full, (hi == m) && (lo == wlo));
        int sl = __ffs(wsb) - 1;
        u64 xy, zz;
        asm volatile("ld.shared.b64 %0, [%1];" : "=l"(xy) : "r"(slb + sl * SLOTB + 8));
        asm volatile("ld.shared.b64 %0, [%1];" : "=l"(zz) : "r"(slb + sl * SLOTB + 16));
        unsigned ux, uy, uz, up;
        UNPK2(ux, uy, xy);
        UNPK2(uz, up, zz);
        lx = __uint_as_float(ux);
        ly = __uint_as_float(uy);
        lz = __uint_as_float(uz);

        if (rank == 0 && t == 0) {
            int g = cloud * NN + win;
            g_cidx[cloud * M1 + s] = g;  outf[cloud * M1 + s] = (float)g;
            if (cloud == 0 && s < M2) {
                g_cidx[BB * M1 + s] = g;  outf[BB * M1 + s] = (float)g;
            }
            if (cloud == 1 && s < (OVSZ - M2)) {
                g_cidx[BB * M1 + M2 + s] = g;  outf[BB * M1 + M2 + s] = (float)g;
            }
        }
    }

    // No CTA may exit while peers' st.async toward it could be in flight.
    asm volatile("barrier.cluster.arrive.aligned;" ::: "memory");
    asm volatile("barrier.cluster.wait.aligned;"   ::: "memory");
}

// -------------------------------------------------------------------------
// kNN: one query per warp, lane-distributed sorted top-16 (round-6 design).
// Runs ONLY the 8192 base-region queries; extras are duplicated after.
// -------------------------------------------------------------------------
#define KNN_T 256
#define WPB (KNN_T / 32)

__global__ void __launch_bounds__(KNN_T)
knn_kernel(const float* __restrict__ pos,
           float* __restrict__ rowf, float* __restrict__ colf)
{
    const int lane = threadIdx.x & 31;
    const int wid  = threadIdx.x >> 5;
    const unsigned full = 0xffffffffu;

    const int posc = blockIdx.x * WPB + wid;      // base-region position
    const int b    = posc >> 10;                  // cloud id

    const float* __restrict__ p = pos + (size_t)b * NN * 3;

    const int qi = g_cidx[posc] & (NN - 1);
    const float qx = __ldg(&p[3 * qi + 0]);
    const float qy = __ldg(&p[3 * qi + 1]);
    const float qz = __ldg(&p[3 * qi + 2]);

    u64 mykey = ~0ull;                            // lanes 0..15: sorted list
    u64 thr   = ~0ull;

    for (int trip = 0; trip < NN / 32; ++trip) {
        const int j = trip * 32 + lane;
        float dx = __ldg(&p[3 * j + 0]) - qx;
        float dy = __ldg(&p[3 * j + 1]) - qy;
        float dz = __ldg(&p[3 * j + 2]) - qz;
        float d = __fadd_rn(__fadd_rn(__fmul_rn(dx, dx), __fmul_rn(dy, dy)),
                            __fmul_rn(dz, dz));
        u64 ckey = ((u64)__float_as_uint(d) << 32) | (unsigned)j;

        unsigned qmask = __ballot_sync(full, ckey < thr);
        while (qmask) {
            int leader = __ffs(qmask) - 1;
            qmask &= qmask - 1;
            u64 cand = __shfl_sync(full, ckey, leader);
            if (cand < thr) {
                unsigned below = __ballot_sync(full, mykey < cand) & 0xffffu;
                int pos16 = __popc(below);
                u64 up = __shfl_up_sync(full, mykey, 1);
                if (lane >= pos16) mykey = (lane == pos16) ? cand : up;
                thr = __shfl_sync(full, mykey, 15);
            }
        }
    }

    if (lane < KNN && rowf != nullptr) {
        rowf[posc * KNN + lane] = (float)posc;
        colf[posc * KNN + lane] = (float)(b * NN + (int)(unsigned)(mykey & 0xffffffffu));
    }
}

// -------------------------------------------------------------------------
// Extra-region duplication (same point/cloud -> identical col row).
// -------------------------------------------------------------------------
__global__ void dup_kernel(float* __restrict__ rowf, float* __restrict__ colf)
{
    int i = blockIdx.x * blockDim.x + threadIdx.x;
    if (i >= OVSZ * KNN) return;
    int j = i / KNN, k = i - j * KNN;
    int dst = BB * M1 + j;
    int src = (j < M2) ? j : (M1 + (j - M2));
    rowf[dst * KNN + k] = (float)dst;
    colf[dst * KNN + k] = colf[src * KNN + k];
}

// -------------------------------------------------------------------------
extern "C" void kernel_launch(void* const* d_in, const int* in_sizes, int n_in,
                              void* d_out, int out_size)
{
    const float* pos = (const float*)d_in[0];
    int best = -1;
    for (int i = 0; i < n_in; ++i) {
        if (in_sizes[i] > best) { best = in_sizes[i]; pos = (const float*)d_in[i]; }
    }

    float* outf = (float*)d_out;
    float* rowf = nullptr;
    float* colf = nullptr;
    if (out_size >= MTOT + 2 * MTOT * KNN) {
        rowf = outf + MTOT;
        colf = outf + MTOT + (size_t)MTOT * KNN;
    }

    fps_kernel<<<BB * CPC, FT>>>(pos, outf);

    knn_kernel<<<(BB * M1) / WPB, KNN_T>>>(pos, rowf, colf);

    if (rowf != nullptr)
        dup_kernel<<<(OVSZ * KNN + 255) / 256, 256>>>(rowf, colf);
}